// round 1
// baseline (speedup 1.0000x reference)
#include <cuda_runtime.h>
#include <math.h>

// AFT-full, separable-exponent rewrite:
//   q = sigmoid(x Wq^T + bq)
//   P[t,j]   = exp(pos_bias[t,j])                        (shared over batch, d)
//   E[b,j,d] = exp(k[b,j,d]),  Z = [E*v | E]  in [B, 512, 256]
//   O2[b]    = P @ Z[b]   -> num = O2[:, :128], den = O2[:, 128:]
//   out = q * num / den      (stabilizer cancels exactly in the ratio)

#define BSZ   4
#define SEQ   512
#define DIM   128
#define NROW  (BSZ * SEQ)      // 2048
#define PROJN 384              // q|k|v concatenated
#define ZN    256              // E*v | E

// Scratch (static __device__ — no allocation in kernel_launch)
__device__ float g_q [NROW * DIM];
__device__ float g_k [NROW * DIM];
__device__ float g_v [NROW * DIM];
__device__ float g_Z [NROW * ZN];
__device__ float g_P [SEQ * SEQ];
__device__ float g_O2[NROW * ZN];

// ---------------------------------------------------------------------------
// Projection GEMM: out[r, n] = sum_d x[r,d] * W_sel[e,d] (+bias in epilogue)
// M=2048, K=128, N=384.  Tiles 64x64, BK=16, 256 threads, 4x4 frags.
// grid = (6, 32)
// ---------------------------------------------------------------------------
__global__ __launch_bounds__(256)
void proj_gemm(const float* __restrict__ x,
               const float* __restrict__ Wq, const float* __restrict__ bq,
               const float* __restrict__ Wk, const float* __restrict__ bk,
               const float* __restrict__ Wv, const float* __restrict__ bv)
{
    __shared__ float As[16][68];   // [k][m], padded
    __shared__ float Bs[16][68];   // [k][n], padded

    const int m0 = blockIdx.y * 64;
    const int n0 = blockIdx.x * 64;
    const int mat = n0 / DIM;            // 0=q, 1=k, 2=v (64-tile never crosses)
    const int e0  = n0 % DIM;
    const float* W    = (mat == 0) ? Wq : (mat == 1) ? Wk : Wv;
    const float* bias = (mat == 0) ? bq : (mat == 1) ? bk : bv;

    const int tid = threadIdx.x;
    const int kk = tid & 15;       // loader: k fast -> coalesced global reads
    const int rr = tid >> 4;
    const int tx = tid & 15;       // compute mapping
    const int ty = tid >> 4;

    float acc[4][4] = {};

    for (int k0 = 0; k0 < DIM; k0 += 16) {
        #pragma unroll
        for (int i = 0; i < 4; i++) {
            int mm = rr + 16 * i;
            As[kk][mm] = x[(m0 + mm) * DIM + k0 + kk];
            Bs[kk][mm] = W[(e0 + mm) * DIM + k0 + kk];
        }
        __syncthreads();
        #pragma unroll
        for (int k = 0; k < 16; k++) {
            float4 a = *(const float4*)&As[k][ty * 4];
            float4 b = *(const float4*)&Bs[k][tx * 4];
            float av[4] = {a.x, a.y, a.z, a.w};
            float bv4[4] = {b.x, b.y, b.z, b.w};
            #pragma unroll
            for (int i = 0; i < 4; i++)
                #pragma unroll
                for (int j = 0; j < 4; j++)
                    acc[i][j] = fmaf(av[i], bv4[j], acc[i][j]);
        }
        __syncthreads();
    }

    #pragma unroll
    for (int i = 0; i < 4; i++) {
        int m = m0 + ty * 4 + i;
        #pragma unroll
        for (int j = 0; j < 4; j++) {
            int e = e0 + tx * 4 + j;
            float val = acc[i][j] + bias[e];
            if (mat == 0)      g_q[m * DIM + e] = 1.0f / (1.0f + expf(-val));
            else if (mat == 1) g_k[m * DIM + e] = val;
            else               g_v[m * DIM + e] = val;
        }
    }
}

// ---------------------------------------------------------------------------
// Prep: P = exp(pos_bias); Z = [exp(k)*v | exp(k)]
// One kernel, two independent index ranges.
// total = SEQ*SEQ + NROW*DIM = 262144 + 262144
// ---------------------------------------------------------------------------
__global__ __launch_bounds__(256)
void prep_kernel(const float* __restrict__ pos_bias)
{
    int idx = blockIdx.x * blockDim.x + threadIdx.x;
    const int NP = SEQ * SEQ;
    if (idx < NP) {
        g_P[idx] = expf(pos_bias[idx]);
    } else {
        int i = idx - NP;                 // [0, NROW*DIM)
        int row = i >> 7;                 // /128
        int d   = i & 127;
        float e = expf(g_k[i]);
        g_Z[row * ZN + d]       = e * g_v[i];
        g_Z[row * ZN + DIM + d] = e;
    }
}

// ---------------------------------------------------------------------------
// AFT GEMM: O2[b] = P @ Z[b].  M=512, K=512, N=256 per batch.
// Tiles 64x64, BK=16, 256 threads, 4x4 frags. grid = (4, 8, 4)
// ---------------------------------------------------------------------------
__global__ __launch_bounds__(256)
void aft_gemm()
{
    __shared__ float As[16][68];   // [k][m]
    __shared__ float Bs[16][68];   // [k][n]

    const int b  = blockIdx.z;
    const int m0 = blockIdx.y * 64;
    const int n0 = blockIdx.x * 64;
    const float* __restrict__ Zb = g_Z + b * SEQ * ZN;

    const int tid = threadIdx.x;
    const int akk = tid & 15, arr = tid >> 4;    // A loader: k fast (coalesced)
    const int bnn = tid & 63, bkk = tid >> 6;    // B loader: n fast (coalesced)
    const int tx  = tid & 15, ty  = tid >> 4;

    float acc[4][4] = {};

    for (int j0 = 0; j0 < SEQ; j0 += 16) {
        #pragma unroll
        for (int i = 0; i < 4; i++) {
            int mm = arr + 16 * i;
            As[akk][mm] = g_P[(m0 + mm) * SEQ + j0 + akk];
        }
        #pragma unroll
        for (int i = 0; i < 4; i++) {
            int k = bkk + 4 * i;
            Bs[k][bnn] = Zb[(j0 + k) * ZN + n0 + bnn];
        }
        __syncthreads();
        #pragma unroll
        for (int k = 0; k < 16; k++) {
            float4 a = *(const float4*)&As[k][ty * 4];
            float4 bb = *(const float4*)&Bs[k][tx * 4];
            float av[4] = {a.x, a.y, a.z, a.w};
            float bv4[4] = {bb.x, bb.y, bb.z, bb.w};
            #pragma unroll
            for (int i = 0; i < 4; i++)
                #pragma unroll
                for (int j = 0; j < 4; j++)
                    acc[i][j] = fmaf(av[i], bv4[j], acc[i][j]);
        }
        __syncthreads();
    }

    #pragma unroll
    for (int i = 0; i < 4; i++) {
        int m = m0 + ty * 4 + i;
        #pragma unroll
        for (int j = 0; j < 4; j++) {
            int n = n0 + tx * 4 + j;
            g_O2[(b * SEQ + m) * ZN + n] = acc[i][j];
        }
    }
}

// ---------------------------------------------------------------------------
// Final: out[b,t,d] = q * num / den
// ---------------------------------------------------------------------------
__global__ __launch_bounds__(256)
void final_kernel(float* __restrict__ out)
{
    int i = blockIdx.x * blockDim.x + threadIdx.x;   // [0, NROW*DIM)
    int row = i >> 7;
    int d   = i & 127;
    float num = g_O2[row * ZN + d];
    float den = g_O2[row * ZN + DIM + d];
    out[i] = g_q[i] * (num / den);
}

// ---------------------------------------------------------------------------
extern "C" void kernel_launch(void* const* d_in, const int* in_sizes, int n_in,
                              void* d_out, int out_size)
{
    const float* x   = (const float*)d_in[0];
    const float* Wq  = (const float*)d_in[1];
    const float* bq  = (const float*)d_in[2];
    const float* Wk  = (const float*)d_in[3];
    const float* bk  = (const float*)d_in[4];
    const float* Wv  = (const float*)d_in[5];
    const float* bv  = (const float*)d_in[6];
    const float* pos = (const float*)d_in[7];
    float* out = (float*)d_out;

    proj_gemm<<<dim3(PROJN / 64, NROW / 64), 256>>>(x, Wq, bq, Wk, bk, Wv, bv);

    int prep_total = SEQ * SEQ + NROW * DIM;
    prep_kernel<<<prep_total / 256, 256>>>(pos);

    aft_gemm<<<dim3(ZN / 64, SEQ / 64, BSZ), 256>>>();

    final_kernel<<<(NROW * DIM) / 256, 256>>>(out);
}

// round 2
// speedup vs baseline: 1.0491x; 1.0491x over previous
#include <cuda_runtime.h>
#include <math.h>

// AFT-full, separable-exponent rewrite, FFMA2 (f32x2) GEMMs, 2 launches:
//   Launch 1: q = sigmoid(xWq^T+bq); Z = [exp(k)*v | exp(k)]; P = exp(pos_bias)
//   Launch 2: per batch O = P @ Z ; out = q * num/den fused in epilogue

#define BSZ   4
#define SEQ   512
#define DIM   128
#define NROW  (BSZ * SEQ)      // 2048
#define ZN    256              // E*v | E

typedef unsigned long long ull;

__device__ float g_q[NROW * DIM];
__device__ float g_Z[NROW * ZN];
__device__ float g_P[SEQ * SEQ];

__device__ __forceinline__ void ffma2(ull &d, ull a, ull b) {
    asm("fma.rn.f32x2 %0, %1, %2, %0;" : "+l"(d) : "l"(a), "l"(b));
}
__device__ __forceinline__ float2 unpk(ull v) {
    float2 f; asm("mov.b64 {%0, %1}, %2;" : "=f"(f.x), "=f"(f.y) : "l"(v)); return f;
}

// ---------------------------------------------------------------------------
// Launch 1. Blocks 0..127: QKV projection, 32 rows x 64 e-cols per block.
//           Blocks 128..159: P = exp(pos_bias), 8192 floats each.
// ---------------------------------------------------------------------------
__global__ __launch_bounds__(256)
void proj_prep(const float* __restrict__ x,
               const float* __restrict__ Wq, const float* __restrict__ bq,
               const float* __restrict__ Wk, const float* __restrict__ bk,
               const float* __restrict__ Wv, const float* __restrict__ bv,
               const float* __restrict__ pos)
{
    const int blk = blockIdx.x;
    const int tid = threadIdx.x;

    if (blk >= 128) {                       // ---- P = exp(pos_bias) ----
        const int base = (blk - 128) * 8192;
        #pragma unroll
        for (int j = 0; j < 8; j++) {
            int i = base + (j * 256 + tid) * 4;
            float4 p = *(const float4*)&pos[i];
            float4 o;
            o.x = __expf(p.x); o.y = __expf(p.y);
            o.z = __expf(p.z); o.w = __expf(p.w);
            *(float4*)&g_P[i] = o;
        }
        return;
    }

    // ---- projection GEMM ----
    const int m0 = (blk >> 1) * 32;         // row tile
    const int e0 = (blk & 1) * 64;          // d-col tile

    __shared__ float As2[32][66];           // x, duplicated pairs [k][2m]
    __shared__ float Bq[32][66], Bk[32][66], Bv[32][66];  // [k][e]

    const int w  = tid >> 5;                // warp: e-slice [e0+w*8, +8)
    const int l  = tid & 31;
    const int mg = l >> 2;                  // 8 groups of 4 m-rows
    const int dg = l & 3;                   // 4 groups of 2 e-cols

    ull aq[4] = {0,0,0,0}, ak[4] = {0,0,0,0}, av[4] = {0,0,0,0};

    const int kk = tid & 31;                // loader mapping (k fast: coalesced)
    const int s0 = tid >> 5;

    for (int k0 = 0; k0 < DIM; k0 += 32) {
        #pragma unroll
        for (int i = 0; i < 4; i++) {
            int mm = s0 + 8 * i;
            float v = x[(m0 + mm) * DIM + k0 + kk];
            As2[kk][2 * mm]     = v;
            As2[kk][2 * mm + 1] = v;
        }
        #pragma unroll
        for (int i = 0; i < 8; i++) {
            int ee = s0 + 8 * i;
            Bq[kk][ee] = Wq[(e0 + ee) * DIM + k0 + kk];
            Bk[kk][ee] = Wk[(e0 + ee) * DIM + k0 + kk];
            Bv[kk][ee] = Wv[(e0 + ee) * DIM + k0 + kk];
        }
        __syncthreads();
        #pragma unroll
        for (int k = 0; k < 32; k++) {
            ull bq2 = *(ull*)&Bq[k][w * 8 + dg * 2];
            ull bk2 = *(ull*)&Bk[k][w * 8 + dg * 2];
            ull bv2 = *(ull*)&Bv[k][w * 8 + dg * 2];
            ull a0 = *(ull*)&As2[k][(mg * 4 + 0) * 2];
            ull a1 = *(ull*)&As2[k][(mg * 4 + 1) * 2];
            ull a2 = *(ull*)&As2[k][(mg * 4 + 2) * 2];
            ull a3 = *(ull*)&As2[k][(mg * 4 + 3) * 2];
            ffma2(aq[0], a0, bq2); ffma2(ak[0], a0, bk2); ffma2(av[0], a0, bv2);
            ffma2(aq[1], a1, bq2); ffma2(ak[1], a1, bk2); ffma2(av[1], a1, bv2);
            ffma2(aq[2], a2, bq2); ffma2(ak[2], a2, bk2); ffma2(av[2], a2, bv2);
            ffma2(aq[3], a3, bq2); ffma2(ak[3], a3, bk2); ffma2(av[3], a3, bv2);
        }
        __syncthreads();
    }

    // epilogue: sigmoid -> g_q ; exp(k) and exp(k)*v -> g_Z
    const int e2 = e0 + w * 8 + dg * 2;
    const float2 bq_v = *(const float2*)&bq[e2];
    const float2 bk_v = *(const float2*)&bk[e2];
    const float2 bv_v = *(const float2*)&bv[e2];
    #pragma unroll
    for (int i = 0; i < 4; i++) {
        const int row = m0 + mg * 4 + i;
        float2 qv = unpk(aq[i]);
        float2 kv = unpk(ak[i]);
        float2 vv = unpk(av[i]);
        qv.x = 1.0f / (1.0f + __expf(-(qv.x + bq_v.x)));
        qv.y = 1.0f / (1.0f + __expf(-(qv.y + bq_v.y)));
        float ex = __expf(kv.x + bk_v.x);
        float ey = __expf(kv.y + bk_v.y);
        vv.x += bv_v.x;  vv.y += bv_v.y;
        *(float2*)&g_q[row * DIM + e2]      = qv;
        *(float2*)&g_Z[row * ZN + e2]       = make_float2(ex * vv.x, ey * vv.y);
        *(float2*)&g_Z[row * ZN + DIM + e2] = make_float2(ex, ey);
    }
}

// ---------------------------------------------------------------------------
// Launch 2. O = P @ Z per batch, num+den accumulated in the same block,
// out = q*num/den in epilogue. Block: 32 m-rows x 64 d-cols (+ den cols).
// grid = (2 d-tiles, 16 m-tiles, 4 batches) = 128 blocks, 256 threads.
// ---------------------------------------------------------------------------
__global__ __launch_bounds__(256)
void aft_out(float* __restrict__ out)
{
    const int b  = blockIdx.z;
    const int m0 = blockIdx.y * 32;
    const int d0 = blockIdx.x * 64;
    const float* __restrict__ Zb = g_Z + b * SEQ * ZN;

    __shared__ float As2[32][66];           // P, duplicated pairs [k][2m]
    __shared__ float BsN[32][64];           // Z num cols  [k][d]
    __shared__ float BsD[32][64];           // Z den cols  [k][d]

    const int tid = threadIdx.x;
    const int w  = tid >> 5;                // warp d-slice [d0+w*8, +8)
    const int l  = tid & 31;
    const int mg = l >> 2;
    const int dg = l & 3;

    ull accN[4] = {0,0,0,0}, accD[4] = {0,0,0,0};

    const int kk = tid & 31;                // A loader
    const int s0 = tid >> 5;
    const int f  = tid & 31;                // B loader

    for (int j0 = 0; j0 < SEQ; j0 += 32) {
        #pragma unroll
        for (int i = 0; i < 4; i++) {
            int mm = s0 + 8 * i;
            float v = g_P[(m0 + mm) * SEQ + j0 + kk];
            As2[kk][2 * mm]     = v;
            As2[kk][2 * mm + 1] = v;
        }
        #pragma unroll
        for (int i = 0; i < 4; i++) {
            int kr = s0 + 8 * i;
            const float* src = &Zb[(j0 + kr) * ZN + d0];
            if (f < 16) *(float4*)&BsN[kr][f * 4]        = *(const float4*)&src[f * 4];
            else        *(float4*)&BsD[kr][(f - 16) * 4] = *(const float4*)&src[128 + (f - 16) * 4];
        }
        __syncthreads();
        #pragma unroll
        for (int k = 0; k < 32; k++) {
            ull bn = *(ull*)&BsN[k][w * 8 + dg * 2];
            ull bd = *(ull*)&BsD[k][w * 8 + dg * 2];
            ull a0 = *(ull*)&As2[k][(mg * 4 + 0) * 2];
            ull a1 = *(ull*)&As2[k][(mg * 4 + 1) * 2];
            ull a2 = *(ull*)&As2[k][(mg * 4 + 2) * 2];
            ull a3 = *(ull*)&As2[k][(mg * 4 + 3) * 2];
            ffma2(accN[0], a0, bn); ffma2(accD[0], a0, bd);
            ffma2(accN[1], a1, bn); ffma2(accD[1], a1, bd);
            ffma2(accN[2], a2, bn); ffma2(accD[2], a2, bd);
            ffma2(accN[3], a3, bn); ffma2(accD[3], a3, bd);
        }
        __syncthreads();
    }

    // fused epilogue: out = q * num / den
    const int d2 = d0 + w * 8 + dg * 2;
    #pragma unroll
    for (int i = 0; i < 4; i++) {
        const int row = b * SEQ + m0 + mg * 4 + i;
        float2 q  = *(const float2*)&g_q[row * DIM + d2];
        float2 n  = unpk(accN[i]);
        float2 dn = unpk(accD[i]);
        *(float2*)&out[row * DIM + d2] = make_float2(q.x * n.x / dn.x,
                                                     q.y * n.y / dn.y);
    }
}

// ---------------------------------------------------------------------------
extern "C" void kernel_launch(void* const* d_in, const int* in_sizes, int n_in,
                              void* d_out, int out_size)
{
    const float* x   = (const float*)d_in[0];
    const float* Wq  = (const float*)d_in[1];
    const float* bq  = (const float*)d_in[2];
    const float* Wk  = (const float*)d_in[3];
    const float* bk  = (const float*)d_in[4];
    const float* Wv  = (const float*)d_in[5];
    const float* bv  = (const float*)d_in[6];
    const float* pos = (const float*)d_in[7];
    float* out = (float*)d_out;

    proj_prep<<<160, 256>>>(x, Wq, bq, Wk, bk, Wv, bv, pos);
    aft_out<<<dim3(2, 16, 4), 256>>>(out);
}